// round 5
// baseline (speedup 1.0000x reference)
#include <cuda_runtime.h>
#include <cstdint>

#define N_NODES 100000
#define N_EDGES 6400000
#define ET      (N_EDGES / 4)   // edges per thread = 4

// ---- scratch (static device allocations are allowed) ----
__device__ unsigned g_col32[N_EDGES];   // 25.6 MB: col indices converted to int32 (int64 path)
__device__ float    g_deg [N_NODES];
__device__ float    g_dinv[N_NODES];
__device__ float    g_xs  [N_NODES];    // dinv[n] * x[n]
__device__ float    g_agg1[N_NODES];    // sum of g_xs[row] per col
__device__ float2   g_zs  [N_NODES];    // dinv[n] * z[n, 0:2]
__device__ int      g_i64;              // 1 if edge_index is int64, 0 if int32

// ---- helpers ----
__device__ __forceinline__ void red_add_f32(float* p, float v) {
    asm volatile("red.global.add.f32 [%0], %1;" :: "l"(p), "f"(v) : "memory");
}
__device__ __forceinline__ void red_add_v2f32(float* p, float a, float b) {
    asm volatile("red.global.add.v2.f32 [%0], {%1, %2};" :: "l"(p), "f"(a), "f"(b) : "memory");
}

// K0: per-node init + dtype detection (device-side, graph-capturable)
__global__ void k_init(const unsigned* __restrict__ edge_words) {
    int n = blockIdx.x * blockDim.x + threadIdx.x;
    if (n < N_NODES) {
        g_deg[n]  = 1.0f;   // self-loop
        g_agg1[n] = 0.0f;
    }
    if (blockIdx.x == 0 && threadIdx.x == 0) {
        // int64 layout: words alternate [lo,hi,lo,hi,...], hi==0 (values < 100000, >=0).
        // int32 layout: odd words are random indices -> virtually impossible all zero.
        int i64 = 1;
        #pragma unroll
        for (int i = 0; i < 64; i++)
            if (edge_words[2 * i + 1] != 0u) i64 = 0;
        g_i64 = i64;
    }
}

// K1: degree histogram over col; also convert col -> int32 when input is int64
__global__ void k_deg(const void* __restrict__ edge) {
    int t = blockIdx.x * blockDim.x + threadIdx.x;
    if (t >= ET) return;
    unsigned c0, c1, c2, c3;
    if (g_i64) {
        const ulonglong2* colp =
            (const ulonglong2*)((const unsigned long long*)edge + N_EDGES);
        ulonglong2 a = colp[2 * t];
        ulonglong2 b = colp[2 * t + 1];
        c0 = (unsigned)a.x; c1 = (unsigned)a.y;
        c2 = (unsigned)b.x; c3 = (unsigned)b.y;
        ((uint4*)g_col32)[t] = make_uint4(c0, c1, c2, c3);
    } else {
        const uint4* colp = (const uint4*)((const unsigned*)edge + N_EDGES);
        uint4 v = colp[t];
        c0 = v.x; c1 = v.y; c2 = v.z; c3 = v.w;
    }
    red_add_f32(&g_deg[c0], 1.0f);
    red_add_f32(&g_deg[c1], 1.0f);
    red_add_f32(&g_deg[c2], 1.0f);
    red_add_f32(&g_deg[c3], 1.0f);
}

// K2: dinv = deg^-1/2 ; xs = dinv * x
__global__ void k_node1(const float* __restrict__ x) {
    int n = blockIdx.x * blockDim.x + threadIdx.x;
    if (n >= N_NODES) return;
    float d = rsqrtf(g_deg[n]);
    g_dinv[n] = d;
    g_xs[n]   = d * x[n];
}

// K3: edge pass A — agg1[col] += xs[row]
__global__ void k_edgeA(const void* __restrict__ edge) {
    int t = blockIdx.x * blockDim.x + threadIdx.x;
    if (t >= ET) return;
    unsigned r0, r1, r2, r3, c0, c1, c2, c3;
    if (g_i64) {
        const ulonglong2* rowp = (const ulonglong2*)edge;
        ulonglong2 a = rowp[2 * t];
        ulonglong2 b = rowp[2 * t + 1];
        r0 = (unsigned)a.x; r1 = (unsigned)a.y;
        r2 = (unsigned)b.x; r3 = (unsigned)b.y;
        uint4 c = ((const uint4*)g_col32)[t];
        c0 = c.x; c1 = c.y; c2 = c.z; c3 = c.w;
    } else {
        uint4 r = ((const uint4*)edge)[t];
        r0 = r.x; r1 = r.y; r2 = r.z; r3 = r.w;
        const uint4* colp = (const uint4*)((const unsigned*)edge + N_EDGES);
        uint4 c = colp[t];
        c0 = c.x; c1 = c.y; c2 = c.z; c3 = c.w;
    }
    float v0 = g_xs[r0];
    float v1 = g_xs[r1];
    float v2 = g_xs[r2];
    float v3 = g_xs[r3];
    red_add_f32(&g_agg1[c0], v0);
    red_add_f32(&g_agg1[c1], v1);
    red_add_f32(&g_agg1[c2], v2);
    red_add_f32(&g_agg1[c3], v3);
}

// K4: per-node MLP: a = dinv*(agg1 + xs)  (self-loop folded in)
//     h1[f] = relu(a*W1[f] + b1[f]) ; z[c] = sum_f W2[c,f]*h1[f]
//     zs = dinv*z ; zero d_out accumulators
__global__ void k_node2(const float* __restrict__ W1, const float* __restrict__ b1,
                        const float* __restrict__ W2, float* __restrict__ out) {
    int n = blockIdx.x * blockDim.x + threadIdx.x;
    if (n >= N_NODES) return;
    float d = g_dinv[n];
    float a = d * (g_agg1[n] + g_xs[n]);
    float z0 = 0.f, z1 = 0.f;
    #pragma unroll
    for (int f = 0; f < 16; f++) {
        float h = fmaxf(fmaf(a, W1[f], b1[f]), 0.f);
        z0 = fmaf(W2[f],      h, z0);
        z1 = fmaf(W2[16 + f], h, z1);
    }
    g_zs[n] = make_float2(d * z0, d * z1);
    ((float2*)out)[n] = make_float2(0.f, 0.f);
}

// K5: edge pass B — out[col, 0:2] += zs[row]  (vector red)
__global__ void k_edgeB(const void* __restrict__ edge, float* __restrict__ out) {
    int t = blockIdx.x * blockDim.x + threadIdx.x;
    if (t >= ET) return;
    unsigned r0, r1, r2, r3, c0, c1, c2, c3;
    if (g_i64) {
        const ulonglong2* rowp = (const ulonglong2*)edge;
        ulonglong2 a = rowp[2 * t];
        ulonglong2 b = rowp[2 * t + 1];
        r0 = (unsigned)a.x; r1 = (unsigned)a.y;
        r2 = (unsigned)b.x; r3 = (unsigned)b.y;
        uint4 c = ((const uint4*)g_col32)[t];
        c0 = c.x; c1 = c.y; c2 = c.z; c3 = c.w;
    } else {
        uint4 r = ((const uint4*)edge)[t];
        r0 = r.x; r1 = r.y; r2 = r.z; r3 = r.w;
        const uint4* colp = (const uint4*)((const unsigned*)edge + N_EDGES);
        uint4 c = colp[t];
        c0 = c.x; c1 = c.y; c2 = c.z; c3 = c.w;
    }
    float2 v0 = g_zs[r0];
    float2 v1 = g_zs[r1];
    float2 v2 = g_zs[r2];
    float2 v3 = g_zs[r3];
    red_add_v2f32(out + 2 * (size_t)c0, v0.x, v0.y);
    red_add_v2f32(out + 2 * (size_t)c1, v1.x, v1.y);
    red_add_v2f32(out + 2 * (size_t)c2, v2.x, v2.y);
    red_add_v2f32(out + 2 * (size_t)c3, v3.x, v3.y);
}

// K6: finalize: out = dinv*(acc + zs) + b2   (zs term = self-loop)
__global__ void k_node3(float* __restrict__ out, const float* __restrict__ b2) {
    int n = blockIdx.x * blockDim.x + threadIdx.x;
    if (n >= N_NODES) return;
    float d = g_dinv[n];
    float2 acc = ((float2*)out)[n];
    float2 zs  = g_zs[n];
    ((float2*)out)[n] = make_float2(fmaf(d, acc.x + zs.x, b2[0]),
                                    fmaf(d, acc.y + zs.y, b2[1]));
}

extern "C" void kernel_launch(void* const* d_in, const int* in_sizes, int n_in,
                              void* d_out, int out_size) {
    const float* x    = (const float*)d_in[0];
    const void*  edge = d_in[1];            // int64 or int32, detected on device
    const float* W1   = (const float*)d_in[2];
    const float* b1   = (const float*)d_in[3];
    const float* W2   = (const float*)d_in[4];
    const float* b2   = (const float*)d_in[5];
    float* out = (float*)d_out;

    const int NT = 256;
    const int nodeBlocks = (N_NODES + NT - 1) / NT;   // 391
    const int edgeBlocks = (ET + NT - 1) / NT;        // 6250

    k_init <<<nodeBlocks, NT>>>((const unsigned*)edge);
    k_deg  <<<edgeBlocks, NT>>>(edge);
    k_node1<<<nodeBlocks, NT>>>(x);
    k_edgeA<<<edgeBlocks, NT>>>(edge);
    k_node2<<<nodeBlocks, NT>>>(W1, b1, W2, out);
    k_edgeB<<<edgeBlocks, NT>>>(edge, out);
    k_node3<<<nodeBlocks, NT>>>(out, b2);
}

// round 6
// speedup vs baseline: 1.0048x; 1.0048x over previous
#include <cuda_runtime.h>
#include <cstdint>

#define N_NODES 100000
#define N_EDGES 6400000
#define ET      (N_EDGES / 4)   // edges per thread = 4

// ---- scratch (static device allocations are allowed) ----
__device__ unsigned g_col32[N_EDGES];   // 25.6 MB: col indices converted to int32 (int64 path)
__device__ float    g_deg [N_NODES];
__device__ float    g_dinv[N_NODES];
__device__ float    g_xs  [N_NODES];    // dinv[n] * x[n]
__device__ float    g_agg1[N_NODES];    // sum of g_xs[row] per col
__device__ float2   g_zs  [N_NODES];    // dinv[n] * z[n, 0:2]
__device__ int      g_i64;              // 1 if edge_index is int64, 0 if int32

// ---- helpers ----
__device__ __forceinline__ void red_add_f32(float* p, float v) {
    asm volatile("red.global.add.f32 [%0], %1;" :: "l"(p), "f"(v) : "memory");
}
__device__ __forceinline__ void red_add_v2f32(float* p, float a, float b) {
    asm volatile("red.global.add.v2.f32 [%0], {%1, %2};" :: "l"(p), "f"(a), "f"(b) : "memory");
}

// K0: per-node init + dtype detection (device-side, graph-capturable)
__global__ void k_init(const unsigned* __restrict__ edge_words) {
    int n = blockIdx.x * blockDim.x + threadIdx.x;
    if (n < N_NODES) {
        g_deg[n]  = 1.0f;   // self-loop
        g_agg1[n] = 0.0f;
    }
    if (blockIdx.x == 0 && threadIdx.x == 0) {
        // int64 layout: words alternate [lo,hi,lo,hi,...], hi==0 (values < 100000, >=0).
        // int32 layout: odd words are random indices -> virtually impossible all zero.
        int i64 = 1;
        #pragma unroll
        for (int i = 0; i < 64; i++)
            if (edge_words[2 * i + 1] != 0u) i64 = 0;
        g_i64 = i64;
    }
}

// K1: degree histogram over col; also convert col -> int32 when input is int64
__global__ void k_deg(const void* __restrict__ edge) {
    int t = blockIdx.x * blockDim.x + threadIdx.x;
    if (t >= ET) return;
    unsigned c0, c1, c2, c3;
    if (g_i64) {
        const ulonglong2* colp =
            (const ulonglong2*)((const unsigned long long*)edge + N_EDGES);
        ulonglong2 a = colp[2 * t];
        ulonglong2 b = colp[2 * t + 1];
        c0 = (unsigned)a.x; c1 = (unsigned)a.y;
        c2 = (unsigned)b.x; c3 = (unsigned)b.y;
        ((uint4*)g_col32)[t] = make_uint4(c0, c1, c2, c3);
    } else {
        const uint4* colp = (const uint4*)((const unsigned*)edge + N_EDGES);
        uint4 v = colp[t];
        c0 = v.x; c1 = v.y; c2 = v.z; c3 = v.w;
    }
    red_add_f32(&g_deg[c0], 1.0f);
    red_add_f32(&g_deg[c1], 1.0f);
    red_add_f32(&g_deg[c2], 1.0f);
    red_add_f32(&g_deg[c3], 1.0f);
}

// K2: dinv = deg^-1/2 ; xs = dinv * x
__global__ void k_node1(const float* __restrict__ x) {
    int n = blockIdx.x * blockDim.x + threadIdx.x;
    if (n >= N_NODES) return;
    float d = rsqrtf(g_deg[n]);
    g_dinv[n] = d;
    g_xs[n]   = d * x[n];
}

// K3: edge pass A — agg1[col] += xs[row]
__global__ void k_edgeA(const void* __restrict__ edge) {
    int t = blockIdx.x * blockDim.x + threadIdx.x;
    if (t >= ET) return;
    unsigned r0, r1, r2, r3, c0, c1, c2, c3;
    if (g_i64) {
        const ulonglong2* rowp = (const ulonglong2*)edge;
        ulonglong2 a = rowp[2 * t];
        ulonglong2 b = rowp[2 * t + 1];
        r0 = (unsigned)a.x; r1 = (unsigned)a.y;
        r2 = (unsigned)b.x; r3 = (unsigned)b.y;
        uint4 c = ((const uint4*)g_col32)[t];
        c0 = c.x; c1 = c.y; c2 = c.z; c3 = c.w;
    } else {
        uint4 r = ((const uint4*)edge)[t];
        r0 = r.x; r1 = r.y; r2 = r.z; r3 = r.w;
        const uint4* colp = (const uint4*)((const unsigned*)edge + N_EDGES);
        uint4 c = colp[t];
        c0 = c.x; c1 = c.y; c2 = c.z; c3 = c.w;
    }
    float v0 = g_xs[r0];
    float v1 = g_xs[r1];
    float v2 = g_xs[r2];
    float v3 = g_xs[r3];
    red_add_f32(&g_agg1[c0], v0);
    red_add_f32(&g_agg1[c1], v1);
    red_add_f32(&g_agg1[c2], v2);
    red_add_f32(&g_agg1[c3], v3);
}

// K4: per-node MLP: a = dinv*(agg1 + xs)  (self-loop folded in)
//     h1[f] = relu(a*W1[f] + b1[f]) ; z[c] = sum_f W2[c,f]*h1[f]
//     zs = dinv*z ; zero d_out accumulators
__global__ void k_node2(const float* __restrict__ W1, const float* __restrict__ b1,
                        const float* __restrict__ W2, float* __restrict__ out) {
    int n = blockIdx.x * blockDim.x + threadIdx.x;
    if (n >= N_NODES) return;
    float d = g_dinv[n];
    float a = d * (g_agg1[n] + g_xs[n]);
    float z0 = 0.f, z1 = 0.f;
    #pragma unroll
    for (int f = 0; f < 16; f++) {
        float h = fmaxf(fmaf(a, W1[f], b1[f]), 0.f);
        z0 = fmaf(W2[f],      h, z0);
        z1 = fmaf(W2[16 + f], h, z1);
    }
    g_zs[n] = make_float2(d * z0, d * z1);
    ((float2*)out)[n] = make_float2(0.f, 0.f);
}

// K5: edge pass B — out[col, 0:2] += zs[row]  (vector red)
__global__ void k_edgeB(const void* __restrict__ edge, float* __restrict__ out) {
    int t = blockIdx.x * blockDim.x + threadIdx.x;
    if (t >= ET) return;
    unsigned r0, r1, r2, r3, c0, c1, c2, c3;
    if (g_i64) {
        const ulonglong2* rowp = (const ulonglong2*)edge;
        ulonglong2 a = rowp[2 * t];
        ulonglong2 b = rowp[2 * t + 1];
        r0 = (unsigned)a.x; r1 = (unsigned)a.y;
        r2 = (unsigned)b.x; r3 = (unsigned)b.y;
        uint4 c = ((const uint4*)g_col32)[t];
        c0 = c.x; c1 = c.y; c2 = c.z; c3 = c.w;
    } else {
        uint4 r = ((const uint4*)edge)[t];
        r0 = r.x; r1 = r.y; r2 = r.z; r3 = r.w;
        const uint4* colp = (const uint4*)((const unsigned*)edge + N_EDGES);
        uint4 c = colp[t];
        c0 = c.x; c1 = c.y; c2 = c.z; c3 = c.w;
    }
    float2 v0 = g_zs[r0];
    float2 v1 = g_zs[r1];
    float2 v2 = g_zs[r2];
    float2 v3 = g_zs[r3];
    red_add_v2f32(out + 2 * (size_t)c0, v0.x, v0.y);
    red_add_v2f32(out + 2 * (size_t)c1, v1.x, v1.y);
    red_add_v2f32(out + 2 * (size_t)c2, v2.x, v2.y);
    red_add_v2f32(out + 2 * (size_t)c3, v3.x, v3.y);
}

// K6: finalize: out = dinv*(acc + zs) + b2   (zs term = self-loop)
__global__ void k_node3(float* __restrict__ out, const float* __restrict__ b2) {
    int n = blockIdx.x * blockDim.x + threadIdx.x;
    if (n >= N_NODES) return;
    float d = g_dinv[n];
    float2 acc = ((float2*)out)[n];
    float2 zs  = g_zs[n];
    ((float2*)out)[n] = make_float2(fmaf(d, acc.x + zs.x, b2[0]),
                                    fmaf(d, acc.y + zs.y, b2[1]));
}

extern "C" void kernel_launch(void* const* d_in, const int* in_sizes, int n_in,
                              void* d_out, int out_size) {
    const float* x    = (const float*)d_in[0];
    const void*  edge = d_in[1];            // int64 or int32, detected on device
    const float* W1   = (const float*)d_in[2];
    const float* b1   = (const float*)d_in[3];
    const float* W2   = (const float*)d_in[4];
    const float* b2   = (const float*)d_in[5];
    float* out = (float*)d_out;

    const int NT = 256;
    const int nodeBlocks = (N_NODES + NT - 1) / NT;   // 391
    const int edgeBlocks = (ET + NT - 1) / NT;        // 6250

    k_init <<<nodeBlocks, NT>>>((const unsigned*)edge);
    k_deg  <<<edgeBlocks, NT>>>(edge);
    k_node1<<<nodeBlocks, NT>>>(x);
    k_edgeA<<<edgeBlocks, NT>>>(edge);
    k_node2<<<nodeBlocks, NT>>>(W1, b1, W2, out);
    k_edgeB<<<edgeBlocks, NT>>>(edge, out);
    k_node3<<<nodeBlocks, NT>>>(out, b2);
}